// round 1
// baseline (speedup 1.0000x reference)
#include <cuda_runtime.h>
#include <math.h>

#define EMBED 512
#define NBATCH 8
#define QLEN 2048
#define KLEN 4096

// ---------------- scratch (device globals; no allocation) ----------------
__device__ float d_Qm[NBATCH * QLEN * EMBED];                 //  32 MB
__device__ float d_Km[NBATCH * KLEN * EMBED];                 //  64 MB
__device__ float d_Vm[NBATCH * KLEN * EMBED];                 //  64 MB
__device__ float d_E [(size_t)NBATCH * QLEN * KLEN];          // 256 MB
__device__ float d_O [NBATCH * QLEN * EMBED];                 //  32 MB

// ---------------- tiled SGEMM: C = A * op(B) (+ resid + bias) ------------
// A: [M,K] row-major. TRANSB: B is [N,K] row-major (compute A@B^T).
// !TRANSB: B is [K,N] row-major. Batched via blockIdx.z with ll strides.
// Requires M%128==0, N%128==0, K%16==0 (true for all calls here).
template <bool TRANSB, bool EPI>
__global__ void __launch_bounds__(256, 1)
sgemm_kernel(const float* __restrict__ A, const float* __restrict__ B,
             float* __restrict__ C, int M, int N, int K,
             long long sA, long long sB, long long sC,
             const float* __restrict__ resid, const float* __restrict__ bias)
{
    constexpr int BM = 128, BN = 128, BK = 16;
    __shared__ float As[BK][BM];
    __shared__ float Bs[BK][BN];

    const int b = blockIdx.z;
    A += (long long)b * sA;
    B += (long long)b * sB;
    C += (long long)b * sC;
    if (EPI) resid += (long long)b * sC;

    const int m0 = blockIdx.y * BM;
    const int n0 = blockIdx.x * BN;
    const int t  = threadIdx.x;

    const int tx = t & 15;         // 0..15
    const int ty = t >> 4;         // 0..15
    const int rowBase = ty * 8;
    const int colBase = tx * 8;

    float acc[8][8] = {};

    for (int k0 = 0; k0 < K; k0 += BK) {
        // ---- load A tile (BM x BK), store transposed into As[k][m] ----
        #pragma unroll
        for (int it = 0; it < 2; it++) {
            int idx = t + it * 256;          // 0..511 float4s
            int m   = idx >> 2;              // 0..127
            int k4  = (idx & 3) * 4;         // 0,4,8,12
            float4 v = *reinterpret_cast<const float4*>(
                &A[(long long)(m0 + m) * K + k0 + k4]);
            As[k4 + 0][m] = v.x; As[k4 + 1][m] = v.y;
            As[k4 + 2][m] = v.z; As[k4 + 3][m] = v.w;
        }
        // ---- load B tile into Bs[k][n] ----
        if (TRANSB) {
            #pragma unroll
            for (int it = 0; it < 2; it++) {
                int idx = t + it * 256;
                int n   = idx >> 2;
                int k4  = (idx & 3) * 4;
                float4 v = *reinterpret_cast<const float4*>(
                    &B[(long long)(n0 + n) * K + k0 + k4]);
                Bs[k4 + 0][n] = v.x; Bs[k4 + 1][n] = v.y;
                Bs[k4 + 2][n] = v.z; Bs[k4 + 3][n] = v.w;
            }
        } else {
            #pragma unroll
            for (int it = 0; it < 2; it++) {
                int idx = t + it * 256;
                int k   = idx >> 5;              // 0..15
                int n4  = (idx & 31) * 4;        // 0..124
                float4 v = *reinterpret_cast<const float4*>(
                    &B[(long long)(k0 + k) * N + n0 + n4]);
                *reinterpret_cast<float4*>(&Bs[k][n4]) = v;
            }
        }
        __syncthreads();

        // ---- 8x8 register-tile FMA ----
        #pragma unroll
        for (int k = 0; k < BK; k++) {
            float ra[8], rb[8];
            #pragma unroll
            for (int i = 0; i < 8; i++) ra[i] = As[k][rowBase + i];
            #pragma unroll
            for (int j = 0; j < 8; j++) rb[j] = Bs[k][colBase + j];
            #pragma unroll
            for (int i = 0; i < 8; i++)
                #pragma unroll
                for (int j = 0; j < 8; j++)
                    acc[i][j] += ra[i] * rb[j];
        }
        __syncthreads();
    }

    // ---- epilogue / store ----
    #pragma unroll
    for (int i = 0; i < 8; i++) {
        const int m = m0 + rowBase + i;
        #pragma unroll
        for (int j = 0; j < 8; j += 4) {
            const int n = n0 + colBase + j;
            float4 v;
            v.x = acc[i][j + 0]; v.y = acc[i][j + 1];
            v.z = acc[i][j + 2]; v.w = acc[i][j + 3];
            if (EPI) {
                float4 r = *reinterpret_cast<const float4*>(
                    &resid[(long long)m * N + n]);
                float4 bb = *reinterpret_cast<const float4*>(&bias[n]);
                v.x += r.x + bb.x; v.y += r.y + bb.y;
                v.z += r.z + bb.z; v.w += r.w + bb.w;
            }
            *reinterpret_cast<float4*>(&C[(long long)m * N + n]) = v;
        }
    }
}

// ---------------- row softmax over K=4096 with scale 1/sqrt(512) ---------
__inline__ __device__ float warpMax(float v) {
    #pragma unroll
    for (int o = 16; o; o >>= 1) v = fmaxf(v, __shfl_xor_sync(0xffffffffu, v, o));
    return v;
}
__inline__ __device__ float warpSum(float v) {
    #pragma unroll
    for (int o = 16; o; o >>= 1) v += __shfl_xor_sync(0xffffffffu, v, o);
    return v;
}

__global__ void __launch_bounds__(256, 1)
softmax_rows(float* __restrict__ E)
{
    const long long row = blockIdx.x;
    float4* p4 = reinterpret_cast<float4*>(E + row * KLEN);
    const int t = threadIdx.x;
    const float scale = rsqrtf((float)EMBED);

    __shared__ float red[8];

    float4 v[4];
    float mx = -INFINITY;
    #pragma unroll
    for (int i = 0; i < 4; i++) {
        float4 x = p4[t + i * 256];
        x.x *= scale; x.y *= scale; x.z *= scale; x.w *= scale;
        v[i] = x;
        mx = fmaxf(mx, fmaxf(fmaxf(x.x, x.y), fmaxf(x.z, x.w)));
    }
    mx = warpMax(mx);
    if ((t & 31) == 0) red[t >> 5] = mx;
    __syncthreads();
    if (t < 32) {
        float m = (t < 8) ? red[t] : -INFINITY;
        m = warpMax(m);
        if (t == 0) red[0] = m;
    }
    __syncthreads();
    mx = red[0];

    float sum = 0.f;
    #pragma unroll
    for (int i = 0; i < 4; i++) {
        v[i].x = expf(v[i].x - mx); v[i].y = expf(v[i].y - mx);
        v[i].z = expf(v[i].z - mx); v[i].w = expf(v[i].w - mx);
        sum += v[i].x + v[i].y + v[i].z + v[i].w;
    }
    sum = warpSum(sum);
    __syncthreads();
    if ((t & 31) == 0) red[t >> 5] = sum;
    __syncthreads();
    if (t < 32) {
        float s = (t < 8) ? red[t] : 0.f;
        s = warpSum(s);
        if (t == 0) red[0] = s;
    }
    __syncthreads();
    const float inv = 1.f / red[0];

    #pragma unroll
    for (int i = 0; i < 4; i++) {
        v[i].x *= inv; v[i].y *= inv; v[i].z *= inv; v[i].w *= inv;
        p4[t + i * 256] = v[i];
    }
}

// ---------------- launch -------------------------------------------------
extern "C" void kernel_launch(void* const* d_in, const int* in_sizes, int n_in,
                              void* d_out, int out_size)
{
    const float* x  = (const float*)d_in[0];   // [8,2048,512]
    const float* y  = (const float*)d_in[1];   // [8,4096,512]
    const float* Wq = (const float*)d_in[2];   // [512,512]
    const float* Wk = (const float*)d_in[3];
    const float* Wv = (const float*)d_in[4];
    const float* Wo = (const float*)d_in[5];
    const float* bo = (const float*)d_in[6];   // [512]
    float* out = (float*)d_out;                // [8,2048,512]

    float *Qm, *Km, *Vm, *E, *O;
    cudaGetSymbolAddress((void**)&Qm, d_Qm);
    cudaGetSymbolAddress((void**)&Km, d_Km);
    cudaGetSymbolAddress((void**)&Vm, d_Vm);
    cudaGetSymbolAddress((void**)&E,  d_E);
    cudaGetSymbolAddress((void**)&O,  d_O);

    const int MQ = NBATCH * QLEN;  // 16384
    const int MK = NBATCH * KLEN;  // 32768

    // 1-3: projections  (A @ W^T)
    sgemm_kernel<true, false><<<dim3(EMBED / 128, MQ / 128, 1), 256>>>(
        x, Wq, Qm, MQ, EMBED, EMBED, 0, 0, 0, nullptr, nullptr);
    sgemm_kernel<true, false><<<dim3(EMBED / 128, MK / 128, 1), 256>>>(
        y, Wk, Km, MK, EMBED, EMBED, 0, 0, 0, nullptr, nullptr);
    sgemm_kernel<true, false><<<dim3(EMBED / 128, MK / 128, 1), 256>>>(
        y, Wv, Vm, MK, EMBED, EMBED, 0, 0, 0, nullptr, nullptr);

    // 4: energy E_n = Qm_n @ Km_n^T   [2048 x 4096], batched over 8
    sgemm_kernel<true, false><<<dim3(KLEN / 128, QLEN / 128, NBATCH), 256>>>(
        Qm, Km, E, QLEN, KLEN, EMBED,
        (long long)QLEN * EMBED, (long long)KLEN * EMBED,
        (long long)QLEN * KLEN, nullptr, nullptr);

    // 5: softmax rows (scale 1/sqrt(512) applied inside)
    softmax_rows<<<NBATCH * QLEN, 256>>>(E);

    // 6: O_n = A_n @ Vm_n   [2048 x 512], K=4096, batched
    sgemm_kernel<false, false><<<dim3(EMBED / 128, QLEN / 128, NBATCH), 256>>>(
        E, Vm, O, QLEN, EMBED, KLEN,
        (long long)QLEN * KLEN, (long long)KLEN * EMBED,
        (long long)QLEN * EMBED, nullptr, nullptr);

    // 7: out = x + O @ Wo^T + bo
    sgemm_kernel<true, true><<<dim3(EMBED / 128, MQ / 128, 1), 256>>>(
        O, Wo, out, MQ, EMBED, EMBED, 0, 0, 0, x, bo);
}